// round 17
// baseline (speedup 1.0000x reference)
#include <cuda_runtime.h>
#include <cstdint>

// LayerwiseLowRankUplift: out = z + U_l (V_l^T z), per-sample layer l.
// B=2048, H=2048, R=64, L=32.
//
// R15: R13/R14 (41.0us) + T_SAMP 32->64 (one tile ~= one layer):
//   U traffic in K3 ~96MB -> ~48MB, V traffic in K2 ~48MB -> ~24MB.
//   K3 switches to HB=64 (32 h-blocks) to stay under 48KB static smem.
//  K1 setup:  group samples by layer into <=64-sample tiles.
//  K2 proj:   grid (tiles x SPLITK=8); CTA reduces a 256-wide H chunk
//             for 64 samples into g_proj[sp][b][r].
//  K2.5:      g_proj[8][b][r] -> g_projf[b][r].
//  K3 uplift: grid (tiles x H/64); out[64 x 64 cols] = z + proj @ U^T.

#define T_SAMP   64
#define KT       32            // K2 k-tile rows
#define RANK     64
#define L_CAP    64
#define B_CAP    4096
#define MAX_TILES 512
#define SPLITK   8
#define HB       64            // K3 h-block width

#define VSTRIDE  68            // 64-float rows padded (U/V tiles, projS)
#define ZSTRIDE  36            // 32-float rows padded (K2 Z tile)
// K2 stage float layout: V[32][68] at [0,2176), Z[64][36] at [2176,4480)
#define STAGE_F  4480

__device__ int g_order[B_CAP];
__device__ int g_tile_layer[MAX_TILES];
__device__ int g_tile_start[MAX_TILES];
__device__ int g_tile_cnt[MAX_TILES];
__device__ int g_num_tiles;
__device__ float g_proj[SPLITK][B_CAP][RANK];   // 8MB scratch (no atomics)
__device__ float g_projf[B_CAP][RANK];          // 1MB final proj

__device__ __forceinline__ void cp16(float* sdst, const float* gsrc) {
    unsigned s = (unsigned)__cvta_generic_to_shared(sdst);
    asm volatile("cp.async.cg.shared.global [%0], [%1], 16;" :: "r"(s), "l"(gsrc));
}
__device__ __forceinline__ void cp_commit() {
    asm volatile("cp.async.commit_group;");
}
__device__ __forceinline__ void cp_wait1() {
    asm volatile("cp.async.wait_group 1;");
}
__device__ __forceinline__ void cp_wait0() {
    asm volatile("cp.async.wait_group 0;");
}

// D += A(16x8, row) * B(8x8, col), tf32 inputs taken as raw fp32 bits.
__device__ __forceinline__ void mma_tf32(float* c,
                                         float a0, float a1, float a2, float a3,
                                         float b0, float b1)
{
    uint32_t ua0 = __float_as_uint(a0), ua1 = __float_as_uint(a1);
    uint32_t ua2 = __float_as_uint(a2), ua3 = __float_as_uint(a3);
    uint32_t ub0 = __float_as_uint(b0), ub1 = __float_as_uint(b1);
    asm volatile(
        "mma.sync.aligned.m16n8k8.row.col.f32.tf32.tf32.f32 "
        "{%0,%1,%2,%3}, {%4,%5,%6,%7}, {%8,%9}, {%0,%1,%2,%3};\n"
        : "+f"(c[0]), "+f"(c[1]), "+f"(c[2]), "+f"(c[3])
        : "r"(ua0), "r"(ua1), "r"(ua2), "r"(ua3), "r"(ub0), "r"(ub1));
}

// ---------------------------------------------------------------------------
// K1 setup: 1024 threads; lids read once into registers, reused for histogram
// and scatter. Serial work = 32-layer scan on tid 0 only.
// ---------------------------------------------------------------------------
__global__ void __launch_bounds__(1024)
llru_setup_kernel(const int* __restrict__ lids, int B, int L)
{
    __shared__ int cnt[L_CAP];
    __shared__ int lstart[L_CAP];
    __shared__ int tbase[L_CAP];
    __shared__ int scur[L_CAP];
    int tid = threadIdx.x;

    int myl[4], myb[4], n = 0;
    #pragma unroll
    for (int j = 0; j < 4; j++) {
        int b = tid + j * 1024;
        if (b < B) { myb[n] = b; myl[n] = lids[b]; n++; }
    }

    for (int i = tid; i < L_CAP; i += 1024) cnt[i] = 0;
    __syncthreads();

    for (int j = 0; j < n; j++)
        atomicAdd(&cnt[myl[j]], 1);
    __syncthreads();

    if (tid == 0) {
        int acc = 0, nt = 0;
        for (int l = 0; l < L; l++) {
            lstart[l] = acc;
            tbase[l]  = nt;
            nt  += (cnt[l] + T_SAMP - 1) / T_SAMP;
            acc += cnt[l];
        }
        g_num_tiles = nt;
    }
    __syncthreads();

    if (tid < L) {
        int l = tid, base = tbase[l], st = lstart[l], c = cnt[l];
        scur[l] = st;
        for (int j = 0; j * T_SAMP < c; j++) {
            g_tile_layer[base + j] = l;
            g_tile_start[base + j] = st + j * T_SAMP;
            g_tile_cnt[base + j]   = min(T_SAMP, c - j * T_SAMP);
        }
    }
    __syncthreads();

    for (int j = 0; j < n; j++) {
        int p = atomicAdd(&scur[myl[j]], 1);
        g_order[p] = myb[j];
    }
}

// ---------------------------------------------------------------------------
// K2 proj: CTA = (tile g, split sp). Reduce H-chunk [sp*256, (sp+1)*256)
// into g_proj[sp][b][r] for the tile's <=64 samples.
// 8 warps as 4(m) x 2(n): warp owns 16 m-rows x 32 n-cols (4 n-sub-blocks).
// cp.async double-buffered over 8 k-tiles of 32 rows.
// ---------------------------------------------------------------------------
__global__ void __launch_bounds__(256)
llru_proj_kernel(const float* __restrict__ z,
                 const float* __restrict__ v,
                 int H)
{
    int g = blockIdx.x;
    if (g >= g_num_tiles) return;
    const int sp = blockIdx.y;

    const int layer = g_tile_layer[g];
    const int start = g_tile_start[g];
    const int cnt   = g_tile_cnt[g];

    const int tid  = threadIdx.x;
    const int lane = tid & 31;
    const int warp = tid >> 5;
    const int wm   = warp >> 1;         // 0..3 : m-block (16 rows)
    const int wn   = warp & 1;          // 0..1 : n-half (32 cols)
    const int qr   = lane >> 2;
    const int qc   = lane & 3;

    __shared__ int sid[T_SAMP];
    __shared__ __align__(16) float stage[2][STAGE_F];    // 35840 B

    if (tid < T_SAMP)
        sid[tid] = (tid < cnt) ? g_order[start + tid] : g_order[start];
    __syncthreads();

    const float* vL = v + (size_t)layer * H * RANK;

    const int hchunk = H / SPLITK;            // 256
    const int nkt    = hchunk / KT;           // 8
    const int kbase  = sp * hchunk;

    // z cp.async coords: 64x32 = 2048 floats = 512 float4, 2/thread
    const int zr0 = tid >> 3;                 // 0..31
    const int zc4 = (tid & 7) << 2;           // 0..28
    const float* zrowA = z + (size_t)sid[zr0] * H + kbase + zc4;
    const float* zrowB = z + (size_t)sid[zr0 + 32] * H + kbase + zc4;

    auto issue_tile = [&](int t) {
        float* buf = stage[t & 1];
        int k0 = kbase + t * KT;
        // V: 32x64 = 512 float4, 2 per thread
        #pragma unroll
        for (int j = 0; j < 2; j++) {
            int idx  = tid + j * 256;
            int krow = idx >> 4;
            int c4   = (idx & 15) << 2;
            cp16(buf + krow * VSTRIDE + c4,
                 vL + (size_t)(k0 + krow) * RANK + c4);
        }
        cp16(buf + 2176 + zr0 * ZSTRIDE + zc4, zrowA + t * KT);
        cp16(buf + 2176 + (zr0 + 32) * ZSTRIDE + zc4, zrowB + t * KT);
        cp_commit();
    };

    issue_tile(0);
    issue_tile(1);

    float acc[4][4] = {{0.f,0.f,0.f,0.f},{0.f,0.f,0.f,0.f},
                       {0.f,0.f,0.f,0.f},{0.f,0.f,0.f,0.f}};

    for (int t = 0; t < nkt; t++) {
        cp_wait1();
        __syncthreads();

        const float* Vb = stage[t & 1];
        const float* Zb = Vb + 2176;
        const int m0 = wm * 16;
        #pragma unroll
        for (int s = 0; s < 4; s++) {         // 4 k-steps of 8
            int k0 = s * 8;
            float a0 = Zb[(m0 + qr) * ZSTRIDE + k0 + qc];
            float a1 = Zb[(m0 + qr + 8) * ZSTRIDE + k0 + qc];
            float a2 = Zb[(m0 + qr) * ZSTRIDE + k0 + qc + 4];
            float a3 = Zb[(m0 + qr + 8) * ZSTRIDE + k0 + qc + 4];
            #pragma unroll
            for (int nb = 0; nb < 4; nb++) {
                int nbase = wn * 32 + nb * 8;
                float b0 = Vb[(k0 + qc) * VSTRIDE + nbase + qr];
                float b1 = Vb[(k0 + qc + 4) * VSTRIDE + nbase + qr];
                mma_tf32(acc[nb], a0, a1, a2, a3, b0, b1);
            }
        }

        __syncthreads();
        if (t + 2 < nkt) issue_tile(t + 2);
        else             cp_commit();         // keep wait_group(1) exact
    }

    // publish partials
    const int m0 = wm * 16;
    #pragma unroll
    for (int nb = 0; nb < 4; nb++) {
        int col = wn * 32 + nb * 8 + 2 * qc;
        if (m0 + qr < cnt)
            *(float2*)&g_proj[sp][sid[m0 + qr]][col] =
                make_float2(acc[nb][0], acc[nb][1]);
        if (m0 + qr + 8 < cnt)
            *(float2*)&g_proj[sp][sid[m0 + qr + 8]][col] =
                make_float2(acc[nb][2], acc[nb][3]);
    }
}

// ---------------------------------------------------------------------------
// K2.5 reduce: g_projf[b][r] = sum_p g_proj[p][b][r]. Flat float2 grid.
// ---------------------------------------------------------------------------
__global__ void __launch_bounds__(256)
llru_reduce_kernel(int B)
{
    int i = blockIdx.x * 256 + threadIdx.x;     // float2 index
    int ntot = B * (RANK / 2);
    if (i >= ntot) return;

    float2 a = make_float2(0.f, 0.f);
    #pragma unroll
    for (int p = 0; p < SPLITK; p++) {
        const float2* src = (const float2*)&g_proj[p][0][0];
        float2 pp = src[i];
        a.x += pp.x;
        a.y += pp.y;
    }
    ((float2*)&g_projf[0][0])[i] = a;
}

// ---------------------------------------------------------------------------
// K3 uplift: CTA = (tile g, h-block hb). out[64 samp x 64 cols] = z + proj@U^T.
// Prologue: one cp.async group loads U chunk (64x64) + final proj (64x64).
// Warp w owns 8 h-cols [h0 + w*8, +8); loops 4 m-blocks of 16 samples.
// ---------------------------------------------------------------------------
__global__ void __launch_bounds__(256)
llru_uplift_kernel(const float* __restrict__ z,
                   const float* __restrict__ u,
                   float* __restrict__ out,
                   int H)
{
    int g = blockIdx.x;
    if (g >= g_num_tiles) return;
    const int h0 = blockIdx.y * HB;

    const int layer = g_tile_layer[g];
    const int start = g_tile_start[g];
    const int cnt   = g_tile_cnt[g];

    const int tid  = threadIdx.x;
    const int lane = tid & 31;
    const int warp = tid >> 5;
    const int qr   = lane >> 2;
    const int qc   = lane & 3;

    __shared__ int sid[T_SAMP];
    __shared__ __align__(16) float Us[HB][VSTRIDE];          // 17408 B
    __shared__ __align__(16) float projS[T_SAMP][VSTRIDE];   // 17408 B

    if (tid < T_SAMP)
        sid[tid] = (tid < cnt) ? g_order[start + tid] : g_order[start];
    __syncthreads();

    // one async group: U chunk (4 cp16/thread) + final proj (4 cp16/thread)
    const float* uL = u + (size_t)layer * H * RANK;
    #pragma unroll
    for (int j = 0; j < 4; j++) {
        int idx  = tid + j * 256;          // 0..1023
        int hrow = idx >> 4;
        int c4   = (idx & 15) << 2;
        cp16(&Us[hrow][c4], uL + (size_t)(h0 + hrow) * RANK + c4);
    }
    #pragma unroll
    for (int j = 0; j < 4; j++) {
        int idx = tid + j * 256;           // 0..1023
        int s   = idx >> 4;
        int c4  = (idx & 15) << 2;
        cp16(&projS[s][c4], &g_projf[sid[s]][c4]);
    }
    cp_commit();
    cp_wait0();
    __syncthreads();

    const int hloc = warp * 8;             // this warp's 8 h-cols

    #pragma unroll
    for (int mb = 0; mb < 4; mb++) {
        const int m0 = mb * 16;
        float pa[8][4];
        #pragma unroll
        for (int s = 0; s < 8; s++) {
            int k0 = s * 8;
            pa[s][0] = projS[m0 + qr][k0 + qc];
            pa[s][1] = projS[m0 + qr + 8][k0 + qc];
            pa[s][2] = projS[m0 + qr][k0 + qc + 4];
            pa[s][3] = projS[m0 + qr + 8][k0 + qc + 4];
        }
        float acc[4] = {0.f, 0.f, 0.f, 0.f};
        #pragma unroll
        for (int s = 0; s < 8; s++) {
            int k0 = s * 8;
            float b0 = Us[hloc + qr][k0 + qc];
            float b1 = Us[hloc + qr][k0 + qc + 4];
            mma_tf32(acc, pa[s][0], pa[s][1], pa[s][2], pa[s][3], b0, b1);
        }
        int colbase = h0 + hloc + 2 * qc;
        if (m0 + qr < cnt) {
            size_t gidx = (size_t)sid[m0 + qr] * H + colbase;
            float2 zz = *(const float2*)(z + gidx);
            *(float2*)(out + gidx) = make_float2(zz.x + acc[0], zz.y + acc[1]);
        }
        if (m0 + qr + 8 < cnt) {
            size_t gidx = (size_t)sid[m0 + qr + 8] * H + colbase;
            float2 zz = *(const float2*)(z + gidx);
            *(float2*)(out + gidx) = make_float2(zz.x + acc[2], zz.y + acc[3]);
        }
    }
}

extern "C" void kernel_launch(void* const* d_in, const int* in_sizes, int n_in,
                              void* d_out, int out_size)
{
    const float* z    = (const float*)d_in[0];
    const int*   lids = (const int*)d_in[1];
    const float* u    = (const float*)d_in[2];
    const float* v    = (const float*)d_in[3];
    float*       out  = (float*)d_out;

    int B = in_sizes[1];
    int H = in_sizes[0] / B;
    int L = in_sizes[2] / (H * RANK);
    if (L < 1) L = 1;
    if (L > L_CAP) L = L_CAP;

    llru_setup_kernel<<<1, 1024>>>(lids, B, L);

    int ntiles = B / T_SAMP + L;       // upper bound on emitted tiles
    if (ntiles > MAX_TILES) ntiles = MAX_TILES;

    dim3 gridA(ntiles, SPLITK);
    llru_proj_kernel<<<gridA, 256>>>(z, v, H);

    int nred = (B * (RANK / 2) + 255) / 256;
    llru_reduce_kernel<<<nred, 256>>>(B);

    dim3 gridB(ntiles, H / HB);
    llru_uplift_kernel<<<gridB, 256>>>(z, u, out, H);
}